// round 12
// baseline (speedup 1.0000x reference)
#include <cuda_runtime.h>
#include <cuda_bf16.h>
#include <cuda_fp16.h>
#include <cstdint>
#include <math.h>

#define NUSER 50000
#define NPOST 100000
#define NENT  20000
#define NNODE 170000
#define SROWS 400000      // total hs rows over 6 relations
#define DROWS 420000      // total dst rows over 6 relations
#define ETOT  1550000

static inline int cdiv(int a, int b) { return (a + b - 1) / b; }

// ---------------- static scratch ----------------
__device__ float g_f0_post[NPOST*64];
__device__ float g_f0_user[NUSER*64];
__device__ float g_f0_ent [NENT *64];
__device__ float g_f1_post[NPOST*64];
__device__ float g_f1_user[NUSER*64];
__device__ float g_f1_ent [NENT *64];
__device__ __nv_bfloat16 g_xh[(size_t)NNODE*64];
__device__ __nv_bfloat16 g_xl[(size_t)NNODE*64];
__device__ __half g_hs[(size_t)SROWS*128];
__device__ float g_als[SROWS*2];
__device__ float g_ald[DROWS*2];
__device__ float g_s  [DROWS*2];
__device__ float g_e  [ETOT*2];
__device__ float g_u  [12*256];

// ---------------- helpers ----------------
__device__ __forceinline__ void red_add_v4(float* a, float4 v) {
    asm volatile("red.global.add.v4.f32 [%0], {%1,%2,%3,%4};"
                 :: "l"(a), "f"(v.x), "f"(v.y), "f"(v.z), "f"(v.w) : "memory");
}
__device__ __forceinline__ uint32_t smem_u32(const void* p) {
    return (uint32_t)__cvta_generic_to_shared(p);
}
__device__ __forceinline__ void ldsm_x4(uint32_t& r0, uint32_t& r1, uint32_t& r2,
                                        uint32_t& r3, uint32_t a) {
    asm volatile("ldmatrix.sync.aligned.m8n8.x4.shared.b16 {%0,%1,%2,%3}, [%4];"
                 : "=r"(r0), "=r"(r1), "=r"(r2), "=r"(r3) : "r"(a));
}
__device__ __forceinline__ void mma16816(float* c, const uint32_t* a, const uint32_t* b) {
    asm volatile("mma.sync.aligned.m16n8k16.row.col.f32.bf16.bf16.f32 "
                 "{%0,%1,%2,%3}, {%4,%5,%6,%7}, {%8,%9}, {%0,%1,%2,%3};"
                 : "+f"(c[0]), "+f"(c[1]), "+f"(c[2]), "+f"(c[3])
                 : "r"(a[0]), "r"(a[1]), "r"(a[2]), "r"(a[3]), "r"(b[0]), "r"(b[1]));
}
__device__ __forceinline__ void cvt_store(__nv_bfloat16* ph, __nv_bfloat16* pl, float4 v) {
    float f[4] = { v.x, v.y, v.z, v.w };
    __nv_bfloat162 h2[2], l2[2];
#pragma unroll
    for (int i = 0; i < 2; i++) {
        __nv_bfloat16 h0 = __float2bfloat16_rn(f[2*i]);
        __nv_bfloat16 h1 = __float2bfloat16_rn(f[2*i+1]);
        __nv_bfloat16 l0 = __float2bfloat16_rn(f[2*i]   - __bfloat162float(h0));
        __nv_bfloat16 l1 = __float2bfloat16_rn(f[2*i+1] - __bfloat162float(h1));
        h2[i] = __nv_bfloat162(h0, h1);
        l2[i] = __nv_bfloat162(l0, l1);
    }
    ((__nv_bfloat162*)ph)[0] = h2[0]; ((__nv_bfloat162*)ph)[1] = h2[1];
    ((__nv_bfloat162*)pl)[0] = l2[0]; ((__nv_bfloat162*)pl)[1] = l2[1];
}
__device__ __forceinline__ float leaky(float x) { return x > 0.f ? x : 0.2f * x; }

// ================= proj GEMM (fp32 in, bf16-split MMA, fp32 out) =================
#define XS 40

struct GemmSeg { const float* X; const __nv_bfloat16* Xh; const __nv_bfloat16* Xl;
                 const float* W; const float* bias; float* Y; __half* Yh;
                 int N; int K; int relu; };
struct GemmBatch { GemmSeg seg[6]; int off[7]; int nseg; int J; };

__global__ __launch_bounds__(256) void k_gemm_proj(GemmBatch gb) {
    int b = blockIdx.x;
    int sg = 0;
    while (sg + 1 < gb.nseg && b >= gb.off[sg + 1]) sg++;
    const GemmSeg G = gb.seg[sg];
    const int row0 = (b - gb.off[sg]) * 128;
    const int K = G.K, N = G.N, J = gb.J;

    __shared__ __align__(16) __nv_bfloat16 sXh[128*XS];
    __shared__ __align__(16) __nv_bfloat16 sXl[128*XS];
    __shared__ __align__(16) __nv_bfloat16 sWh[64*XS];
    __shared__ __align__(16) __nv_bfloat16 sWl[64*XS];

    const int tid = threadIdx.x;
    const int wid = tid >> 5, lane = tid & 31;
    const int m_base = (wid >> 1) * 32;
    const int n_base = (wid & 1) * 32;

    float acc[2][4][4];
#pragma unroll
    for (int i = 0; i < 2; i++)
#pragma unroll
        for (int j = 0; j < 4; j++)
#pragma unroll
            for (int q = 0; q < 4; q++) acc[i][j][q] = 0.f;

    const int lr = lane & 7, lq = lane >> 3;
    const int a_row = (lq & 1) * 8 + lr;
    const int a_kc  = (lq >> 1) * 8;
    const int b_row = (lq >> 1) * 8 + lr;
    const int b_kc  = (lq & 1) * 8;

    for (int k0 = 0; k0 < K; k0 += 32) {
#pragma unroll
        for (int q = 0; q < 4; q++) {
            int i = tid + q * 256;
            int r = i >> 3, c4 = (i & 7) * 4;
            int row = row0 + r;
            float4 v = make_float4(0.f, 0.f, 0.f, 0.f);
            if (row < N) v = *(const float4*)&G.X[(size_t)row * K + k0 + c4];
            cvt_store(&sXh[r*XS + c4], &sXl[r*XS + c4], v);
        }
#pragma unroll
        for (int q = 0; q < 2; q++) {
            int i = tid + q * 256;
            int r = i >> 3, c4 = (i & 7) * 4;
            float4 v = *(const float4*)&G.W[(size_t)r * K + k0 + c4];
            cvt_store(&sWh[r*XS + c4], &sWl[r*XS + c4], v);
        }
        __syncthreads();

#pragma unroll
        for (int kk = 0; kk < 32; kk += 16) {
            uint32_t Ah[2][4], Al[2][4], Bh[4][2], Bl[4][2];
#pragma unroll
            for (int im = 0; im < 2; im++) {
                int r = m_base + im * 16 + a_row;
                ldsm_x4(Ah[im][0], Ah[im][1], Ah[im][2], Ah[im][3],
                        smem_u32(&sXh[r*XS + kk + a_kc]));
                ldsm_x4(Al[im][0], Al[im][1], Al[im][2], Al[im][3],
                        smem_u32(&sXl[r*XS + kk + a_kc]));
            }
#pragma unroll
            for (int nn = 0; nn < 2; nn++) {
                int r = n_base + nn * 16 + b_row;
                uint32_t r0, r1, r2, r3;
                ldsm_x4(r0, r1, r2, r3, smem_u32(&sWh[r*XS + kk + b_kc]));
                Bh[nn*2][0] = r0; Bh[nn*2][1] = r1;
                Bh[nn*2+1][0] = r2; Bh[nn*2+1][1] = r3;
                ldsm_x4(r0, r1, r2, r3, smem_u32(&sWl[r*XS + kk + b_kc]));
                Bl[nn*2][0] = r0; Bl[nn*2][1] = r1;
                Bl[nn*2+1][0] = r2; Bl[nn*2+1][1] = r3;
            }
#pragma unroll
            for (int im = 0; im < 2; im++)
#pragma unroll
                for (int jn = 0; jn < 4; jn++) {
                    mma16816(acc[im][jn], Ah[im], Bh[jn]);
                    mma16816(acc[im][jn], Al[im], Bh[jn]);
                    mma16816(acc[im][jn], Ah[im], Bl[jn]);
                }
        }
        __syncthreads();
    }

    const int r_lo = lane >> 2;
    const int c_lo = (lane & 3) * 2;
#pragma unroll
    for (int im = 0; im < 2; im++) {
#pragma unroll
        for (int jn = 0; jn < 4; jn++) {
            int col = n_base + jn * 8 + c_lo;
            int row1 = row0 + m_base + im * 16 + r_lo;
            int row2 = row1 + 8;
            float2 bb = make_float2(0.f, 0.f);
            if (G.bias) bb = *(const float2*)&G.bias[col];
            if (row1 < N)
                *(float2*)&G.Y[(size_t)row1 * J + col] =
                    make_float2(acc[im][jn][0] + bb.x, acc[im][jn][1] + bb.y);
            if (row2 < N)
                *(float2*)&G.Y[(size_t)row2 * J + col] =
                    make_float2(acc[im][jn][2] + bb.x, acc[im][jn][3] + bb.y);
        }
    }
}

// ================= hs GEMM: K=64 resident, both 64-col halves per block ======
#define XS2 72
#define SMEM_HS (4 * 128 * XS2 * 2)

__global__ __launch_bounds__(256) void k_gemm_hs(GemmBatch gb) {
    int b = blockIdx.x;
    int sg = 0;
    while (sg + 1 < gb.nseg && b >= gb.off[sg + 1]) sg++;
    const GemmSeg G = gb.seg[sg];
    const int row0 = (b - gb.off[sg]) * 128;
    const int N = G.N;

    extern __shared__ __align__(16) __nv_bfloat16 smem[];
    __nv_bfloat16* sXh = smem;
    __nv_bfloat16* sXl = smem + 128*XS2;
    __nv_bfloat16* sWh = smem + 2*128*XS2;
    __nv_bfloat16* sWl = smem + 3*128*XS2;

    const int tid = threadIdx.x;
    const int wid = tid >> 5, lane = tid & 31;
    const int m_base = (wid >> 1) * 32;
    const int n_base = (wid & 1) * 32;

    // load X tile [128 x 64] h/l
#pragma unroll
    for (int q = 0; q < 4; q++) {
        int i = tid + q * 256;
        int r = i >> 3, c8 = (i & 7) * 8;
        int row = row0 + r;
        uint4 vh = make_uint4(0,0,0,0), vl = make_uint4(0,0,0,0);
        if (row < N) {
            vh = *(const uint4*)&G.Xh[(size_t)row * 64 + c8];
            vl = *(const uint4*)&G.Xl[(size_t)row * 64 + c8];
        }
        *(uint4*)&sXh[r*XS2 + c8] = vh;
        *(uint4*)&sXl[r*XS2 + c8] = vl;
    }
    // load full W [128 x 64] fp32 -> h/l
#pragma unroll
    for (int q = 0; q < 8; q++) {
        int i = tid + q * 256;
        int r = i >> 4, c4 = (i & 15) * 4;
        float4 v = *(const float4*)&G.W[(size_t)r * 64 + c4];
        cvt_store(&sWh[r*XS2 + c4], &sWl[r*XS2 + c4], v);
    }
    __syncthreads();

    const int lr = lane & 7, lq = lane >> 3;
    const int a_row = (lq & 1) * 8 + lr;
    const int a_kc  = (lq >> 1) * 8;
    const int b_row = (lq >> 1) * 8 + lr;
    const int b_kc  = (lq & 1) * 8;
    const int r_lo = lane >> 2;
    const int c_lo = (lane & 3) * 2;

#pragma unroll
    for (int jh = 0; jh < 2; jh++) {
        float acc[2][4][4];
#pragma unroll
        for (int i = 0; i < 2; i++)
#pragma unroll
            for (int j = 0; j < 4; j++)
#pragma unroll
                for (int q = 0; q < 4; q++) acc[i][j][q] = 0.f;

#pragma unroll
        for (int kk = 0; kk < 64; kk += 16) {
            uint32_t Ah[2][4], Al[2][4], Bh[4][2], Bl[4][2];
#pragma unroll
            for (int im = 0; im < 2; im++) {
                int r = m_base + im * 16 + a_row;
                ldsm_x4(Ah[im][0], Ah[im][1], Ah[im][2], Ah[im][3],
                        smem_u32(&sXh[r*XS2 + kk + a_kc]));
                ldsm_x4(Al[im][0], Al[im][1], Al[im][2], Al[im][3],
                        smem_u32(&sXl[r*XS2 + kk + a_kc]));
            }
#pragma unroll
            for (int nn = 0; nn < 2; nn++) {
                int r = jh * 64 + n_base + nn * 16 + b_row;
                uint32_t r0, r1, r2, r3;
                ldsm_x4(r0, r1, r2, r3, smem_u32(&sWh[r*XS2 + kk + b_kc]));
                Bh[nn*2][0] = r0; Bh[nn*2][1] = r1;
                Bh[nn*2+1][0] = r2; Bh[nn*2+1][1] = r3;
                ldsm_x4(r0, r1, r2, r3, smem_u32(&sWl[r*XS2 + kk + b_kc]));
                Bl[nn*2][0] = r0; Bl[nn*2][1] = r1;
                Bl[nn*2+1][0] = r2; Bl[nn*2+1][1] = r3;
            }
#pragma unroll
            for (int im = 0; im < 2; im++)
#pragma unroll
                for (int jn = 0; jn < 4; jn++) {
                    mma16816(acc[im][jn], Ah[im], Bh[jn]);
                    mma16816(acc[im][jn], Al[im], Bh[jn]);
                    mma16816(acc[im][jn], Ah[im], Bl[jn]);
                }
        }
#pragma unroll
        for (int im = 0; im < 2; im++)
#pragma unroll
            for (int jn = 0; jn < 4; jn++) {
                int col = jh * 64 + n_base + jn * 8 + c_lo;
                int row1 = row0 + m_base + im * 16 + r_lo;
                int row2 = row1 + 8;
                if (row1 < N)
                    *(__half2*)&G.Yh[(size_t)row1 * 128 + col] =
                        __floats2half2_rn(acc[im][jn][0], acc[im][jn][1]);
                if (row2 < N)
                    *(__half2*)&G.Yh[(size_t)row2 * 128 + col] =
                        __floats2half2_rn(acc[im][jn][2], acc[im][jn][3]);
            }
    }
}

// ================= fold attention vectors =================
__global__ void k_prep_u_all(const float* __restrict__ a_s, const float* __restrict__ a_d,
                             const float* __restrict__ Ws, const float* __restrict__ Wd,
                             float* __restrict__ u) {
    int b = blockIdx.x;
    int t = threadIdx.x;
    int h = t >> 6, k = t & 63;
    const float* as = a_s + b * 128;
    const float* ad = a_d + b * 128;
    const float* ws = Ws + b * 128 * 64;
    const float* wd = Wd + b * 128 * 64;
    float us = 0.f, ud = 0.f;
#pragma unroll 8
    for (int c = 0; c < 64; c++) {
        us += as[h*64 + c] * ws[(h*64 + c)*64 + k];
        ud += ad[h*64 + c] * wd[(h*64 + c)*64 + k];
    }
    u[b*256 + t] = us;
    u[b*256 + 128 + t] = ud;
}

// ============ cvt + al (8 threads/row) + fused layer init ============
struct AlJob { const float* u; float* out; };
struct AlSeg { const float* x; __nv_bfloat16* xh; __nv_bfloat16* xl;
               int N; int relu; int njobs; AlJob job[6]; };
struct AlBatch {
    AlSeg seg[3]; int off[4];
    // fused init region
    float *nbP, *nbU, *nbE, *s;
    const float *bP0, *bP1, *bP2, *bU0, *bU1, *bE0;
    int iU, iE, iMS, iEnd;
};

__global__ __launch_bounds__(256) void k_cvt_al2(AlBatch ab) {
    int b = blockIdx.x;
    if (b < ab.off[3]) {
        int sg = 0;
        while (sg + 1 < 3 && b >= ab.off[sg + 1]) sg++;
        const AlSeg S = ab.seg[sg];
        __shared__ float su[6*128];
        for (int i = threadIdx.x; i < S.njobs * 128; i += 256)
            su[i] = S.job[i >> 7].u[i & 127];
        __syncthreads();
        int t = threadIdx.x;
        int rowIdx = (b - ab.off[sg]) * 32 + (t >> 3);
        int sub = t & 7;
        int row = min(rowIdx, S.N - 1);
        int c0 = sub * 8;
        float4 v0 = *(const float4*)&S.x[(size_t)row * 64 + c0];
        float4 v1 = *(const float4*)&S.x[(size_t)row * 64 + c0 + 4];
        if (S.relu) {
            v0.x = fmaxf(v0.x, 0.f); v0.y = fmaxf(v0.y, 0.f);
            v0.z = fmaxf(v0.z, 0.f); v0.w = fmaxf(v0.w, 0.f);
            v1.x = fmaxf(v1.x, 0.f); v1.y = fmaxf(v1.y, 0.f);
            v1.z = fmaxf(v1.z, 0.f); v1.w = fmaxf(v1.w, 0.f);
        }
        float xr[8] = { v0.x, v0.y, v0.z, v0.w, v1.x, v1.y, v1.z, v1.w };
        // bf16 hi/lo
        uint32_t hw[4], lw[4];
#pragma unroll
        for (int j = 0; j < 4; j++) {
            float f0 = xr[2*j], f1 = xr[2*j+1];
            __nv_bfloat16 h0 = __float2bfloat16_rn(f0);
            __nv_bfloat16 h1 = __float2bfloat16_rn(f1);
            __nv_bfloat16 l0 = __float2bfloat16_rn(f0 - __bfloat162float(h0));
            __nv_bfloat16 l1 = __float2bfloat16_rn(f1 - __bfloat162float(h1));
            __nv_bfloat162 hp(h0, h1), lp(l0, l1);
            hw[j] = *(uint32_t*)&hp; lw[j] = *(uint32_t*)&lp;
        }
        if (rowIdx < S.N) {
            *(uint4*)&S.xh[(size_t)row*64 + c0] = make_uint4(hw[0], hw[1], hw[2], hw[3]);
            *(uint4*)&S.xl[(size_t)row*64 + c0] = make_uint4(lw[0], lw[1], lw[2], lw[3]);
        }
        for (int j = 0; j < S.njobs; j++) {
            const float* uu = su + j * 128;
            float d0 = 0.f, d1 = 0.f;
#pragma unroll
            for (int k = 0; k < 8; k++) {
                d0 += xr[k] * uu[c0 + k];
                d1 += xr[k] * uu[64 + c0 + k];
            }
#pragma unroll
            for (int off = 4; off; off >>= 1) {
                d0 += __shfl_xor_sync(0xFFFFFFFFu, d0, off);
                d1 += __shfl_xor_sync(0xFFFFFFFFu, d1, off);
            }
            if (sub == 0 && rowIdx < S.N)
                *(float2*)&S.job[j].out[(size_t)rowIdx * 2] = make_float2(d0, d1);
        }
    } else {
        int b2 = b - ab.off[3];
        int t = threadIdx.x;
        if (b2 < ab.iU) {
            int i = b2 * 256 + t; int c = i & 63;
            ab.nbP[i] = ab.bP0[c] + ab.bP1[c] + ab.bP2[c];
        } else if (b2 < ab.iE) {
            int i = (b2 - ab.iU) * 256 + t; int c = i & 63;
            ab.nbU[i] = ab.bU0[c] + ab.bU1[c];
        } else if (b2 < ab.iMS) {
            int i = (b2 - ab.iE) * 256 + t; int c = i & 63;
            ab.nbE[i] = ab.bE0[c];
        } else {
            int i = (b2 - ab.iMS) * 256 + t;
            if (i < DROWS * 2) ab.s[i] = 0.f;
        }
    }
}

// ================= batched edge passes =================
struct EdgeSeg {
    const int* src; const int* dst;
    float* e; const float* als; const float* ald;
    float* s; const __half* hs; float* nb;
    int E;
};
struct EdgeBatch { EdgeSeg seg[6]; int offA[7]; int offC[7]; };

__global__ __launch_bounds__(256) void k_edge_ps(EdgeBatch eb) {
    int b = blockIdx.x;
    int sg = 0;
    while (sg + 1 < 6 && b >= eb.offA[sg + 1]) sg++;
    const EdgeSeg S = eb.seg[sg];
    int e = (b - eb.offA[sg]) * 256 + threadIdx.x;
    if (e >= S.E) return;
    int sN = S.src[e], dN = S.dst[e];
    float2 a  = ((const float2*)S.als)[sN];
    float2 bb = ((const float2*)S.ald)[dN];
    float p0 = __expf(leaky(a.x + bb.x) - 10.f);
    float p1 = __expf(leaky(a.y + bb.y) - 10.f);
    ((float2*)S.e)[e] = make_float2(p0, p1);
    atomicAdd(&S.s[dN*2],     p0);
    atomicAdd(&S.s[dN*2 + 1], p1);
}

__global__ __launch_bounds__(256) void k_edge_c_b(EdgeBatch eb) {
    int b = blockIdx.x;
    int sg = 0;
    while (sg + 1 < 6 && b >= eb.offC[sg + 1]) sg++;
    const EdgeSeg S = eb.seg[sg];
    int t = (b - eb.offC[sg]) * 256 + threadIdx.x;
    int e = t >> 3, lane = t & 7;
    if (e >= S.E) return;
    int sN = S.src[e], dN = S.dst[e];
    float2 p  = ((const float2*)S.e)[e];
    float2 ss = ((const float2*)S.s)[dN];
    float a0 = 0.5f * p.x / (ss.x + 1e-16f);
    float a1 = 0.5f * p.y / (ss.y + 1e-16f);
    const __half* hr = S.hs + (size_t)sN * 128;
    int c0 = lane * 8;
    uint4 u0 = *(const uint4*)&hr[c0];
    uint4 u1 = *(const uint4*)&hr[64 + c0];
    const __half2* h0 = (const __half2*)&u0;
    const __half2* h1 = (const __half2*)&u1;
    float o[8];
#pragma unroll
    for (int j = 0; j < 4; j++) {
        float2 f0 = __half22float2(h0[j]);
        float2 f1 = __half22float2(h1[j]);
        o[2*j]   = a0*f0.x + a1*f1.x;
        o[2*j+1] = a0*f0.y + a1*f1.y;
    }
    float* base = S.nb + (size_t)dN * 64 + c0;
    red_add_v4(base,     make_float4(o[0], o[1], o[2], o[3]));
    red_add_v4(base + 4, make_float4(o[4], o[5], o[6], o[7]));
}

// ================= fused classifier =================
__global__ __launch_bounds__(256) void k_cls(const float* __restrict__ hp,
                      const float* __restrict__ w1, const float* __restrict__ b1,
                      const float* __restrict__ w2, const float* __restrict__ b2,
                      float* __restrict__ out, int N) {
    __shared__ float sw1[32*64];
    __shared__ float sb1[32];
    __shared__ float sw2[32];
    __shared__ float sb2;
    for (int i = threadIdx.x; i < 2048; i += blockDim.x) sw1[i] = w1[i];
    if (threadIdx.x < 32) { sb1[threadIdx.x] = b1[threadIdx.x]; sw2[threadIdx.x] = w2[threadIdx.x]; }
    if (threadIdx.x == 0) sb2 = b2[0];
    __syncthreads();
    int n = blockIdx.x * blockDim.x + threadIdx.x;
    if (n >= N) return;
    float xr[64];
    const float4* xp = (const float4*)(hp + (size_t)n*64);
#pragma unroll
    for (int i = 0; i < 16; i++) {
        float4 v = xp[i];
        xr[i*4]   = fmaxf(v.x, 0.f); xr[i*4+1] = fmaxf(v.y, 0.f);
        xr[i*4+2] = fmaxf(v.z, 0.f); xr[i*4+3] = fmaxf(v.w, 0.f);
    }
    float o = sb2;
#pragma unroll 4
    for (int j = 0; j < 32; j++) {
        float acc = sb1[j];
#pragma unroll
        for (int k = 0; k < 64; k++) acc += xr[k] * sw1[j*64 + k];
        o += fmaxf(acc, 0.f) * sw2[j];
    }
    out[n] = o;
}

// ================= host orchestration =================
struct RelCfg { int sidx, didx, stype, dtype; };
static const RelCfg g_rels[6] = {
    {3, 4,  0, 1},   // publish  user->post
    {5, 6,  0, 1},   // repost   user->post
    {7, 8,  1, 2},   // contain  post->ent
    {9, 10, 0, 0},   // interact user->user
    {11,12, 0, 0},   // follow   user->user
    {13,14, 1, 1},   // similar  post->post
};

extern "C" void kernel_launch(void* const* d_in, const int* in_sizes, int n_in,
                              void* d_out, int out_size)
{
    const float* x_post = (const float*)d_in[0];
    const float* x_user = (const float*)d_in[1];
    const float* x_ent  = (const float*)d_in[2];
    const float* post_w = (const float*)d_in[15];
    const float* post_b = (const float*)d_in[16];
    const float* user_w = (const float*)d_in[17];
    const float* user_b = (const float*)d_in[18];
    const float* ent_w  = (const float*)d_in[19];
    const float* ent_b  = (const float*)d_in[20];
    const float* W_src  = (const float*)d_in[21];
    const float* W_dstP = (const float*)d_in[22];
    const float* a_srcP = (const float*)d_in[23];
    const float* a_dstP = (const float*)d_in[24];
    const float* gat_b  = (const float*)d_in[25];
    const float* cls_w1 = (const float*)d_in[26];
    const float* cls_b1 = (const float*)d_in[27];
    const float* cls_w2 = (const float*)d_in[28];
    const float* cls_b2 = (const float*)d_in[29];

    float *f0p,*f0u,*f0e,*f1p,*f1u,*f1e,*als,*ald,*sb,*ebuf,*ub;
    __nv_bfloat16 *xh, *xl;
    __half* hsb;
    cudaGetSymbolAddress((void**)&f0p, g_f0_post);
    cudaGetSymbolAddress((void**)&f0u, g_f0_user);
    cudaGetSymbolAddress((void**)&f0e, g_f0_ent);
    cudaGetSymbolAddress((void**)&f1p, g_f1_post);
    cudaGetSymbolAddress((void**)&f1u, g_f1_user);
    cudaGetSymbolAddress((void**)&f1e, g_f1_ent);
    cudaGetSymbolAddress((void**)&xh,  g_xh);
    cudaGetSymbolAddress((void**)&xl,  g_xl);
    cudaGetSymbolAddress((void**)&hsb, g_hs);
    cudaGetSymbolAddress((void**)&als, g_als);
    cudaGetSymbolAddress((void**)&ald, g_ald);
    cudaGetSymbolAddress((void**)&sb,  g_s);
    cudaGetSymbolAddress((void**)&ebuf,g_e);
    cudaGetSymbolAddress((void**)&ub,  g_u);

    cudaFuncSetAttribute(k_gemm_hs, cudaFuncAttributeMaxDynamicSharedMemorySize, SMEM_HS);

    const int ncnt[3] = { NUSER, NPOST, NENT };
    const int toff[3] = { 0, NUSER, NUSER + NPOST };

    int E[6], soff[6], doff[6], eoff[6];
    int sacc = 0, dacc = 0, eacc = 0;
    for (int r = 0; r < 6; r++) {
        E[r] = in_sizes[g_rels[r].sidx];
        soff[r] = sacc; sacc += ncnt[g_rels[r].stype];
        doff[r] = dacc; dacc += ncnt[g_rels[r].dtype];
        eoff[r] = eacc; eacc += E[r];
    }

    // fold attention vectors
    k_prep_u_all<<<12, 128>>>(a_srcP, a_dstP, W_src, W_dstP, ub);

    // input projections
    {
        GemmBatch pb;
        pb.J = 64; pb.nseg = 3;
        pb.seg[0] = { x_post, nullptr, nullptr, post_w, post_b, f0p, nullptr, NPOST, 768, 0 };
        pb.seg[1] = { x_user, nullptr, nullptr, user_w, user_b, f0u, nullptr, NUSER, 32, 0 };
        pb.seg[2] = { x_ent,  nullptr, nullptr, ent_w,  ent_b,  f0e, nullptr, NENT,  64, 0 };
        pb.off[0] = 0;
        pb.off[1] = pb.off[0] + cdiv(NPOST, 128);
        pb.off[2] = pb.off[1] + cdiv(NUSER, 128);
        pb.off[3] = pb.off[2] + cdiv(NENT, 128);
        k_gemm_proj<<<pb.off[3], 256>>>(pb);
    }

    float* cur[3] = { f0u, f0p, f0e };
    float* nxt[3] = { f1u, f1p, f1e };

    for (int l = 0; l < 2; l++) {
        int relu = (l == 1);

        // cvt + al + fused init
        {
            AlBatch ab;
            ab.seg[0].x = cur[0]; ab.seg[0].xh = xh + (size_t)toff[0]*64;
            ab.seg[0].xl = xl + (size_t)toff[0]*64;
            ab.seg[0].N = NUSER; ab.seg[0].relu = relu; ab.seg[0].njobs = 6;
            ab.seg[0].job[0] = { ub + (l*6+0)*256,       als + soff[0]*2 };
            ab.seg[0].job[1] = { ub + (l*6+1)*256,       als + soff[1]*2 };
            ab.seg[0].job[2] = { ub + (l*6+3)*256,       als + soff[3]*2 };
            ab.seg[0].job[3] = { ub + (l*6+3)*256 + 128, ald + doff[3]*2 };
            ab.seg[0].job[4] = { ub + (l*6+4)*256,       als + soff[4]*2 };
            ab.seg[0].job[5] = { ub + (l*6+4)*256 + 128, ald + doff[4]*2 };
            ab.seg[1].x = cur[1]; ab.seg[1].xh = xh + (size_t)toff[1]*64;
            ab.seg[1].xl = xl + (size_t)toff[1]*64;
            ab.seg[1].N = NPOST; ab.seg[1].relu = relu; ab.seg[1].njobs = 5;
            ab.seg[1].job[0] = { ub + (l*6+0)*256 + 128, ald + doff[0]*2 };
            ab.seg[1].job[1] = { ub + (l*6+1)*256 + 128, ald + doff[1]*2 };
            ab.seg[1].job[2] = { ub + (l*6+2)*256,       als + soff[2]*2 };
            ab.seg[1].job[3] = { ub + (l*6+5)*256,       als + soff[5]*2 };
            ab.seg[1].job[4] = { ub + (l*6+5)*256 + 128, ald + doff[5]*2 };
            ab.seg[1].job[5] = { nullptr, nullptr };
            ab.seg[2].x = cur[2]; ab.seg[2].xh = xh + (size_t)toff[2]*64;
            ab.seg[2].xl = xl + (size_t)toff[2]*64;
            ab.seg[2].N = NENT; ab.seg[2].relu = relu; ab.seg[2].njobs = 1;
            ab.seg[2].job[0] = { ub + (l*6+2)*256 + 128, ald + doff[2]*2 };
            for (int j = 1; j < 6; j++) ab.seg[2].job[j] = { nullptr, nullptr };
            ab.off[0] = 0;
            ab.off[1] = ab.off[0] + cdiv(NUSER, 32);
            ab.off[2] = ab.off[1] + cdiv(NPOST, 32);
            ab.off[3] = ab.off[2] + cdiv(NENT, 32);
            // fused init region
            ab.nbP = nxt[1]; ab.nbU = nxt[0]; ab.nbE = nxt[2]; ab.s = sb;
            ab.bP0 = gat_b + (l*6+0)*64; ab.bP1 = gat_b + (l*6+1)*64;
            ab.bP2 = gat_b + (l*6+5)*64;
            ab.bU0 = gat_b + (l*6+3)*64; ab.bU1 = gat_b + (l*6+4)*64;
            ab.bE0 = gat_b + (l*6+2)*64;
            ab.iU  = (NPOST * 64) / 256;
            ab.iE  = ab.iU + (NUSER * 64) / 256;
            ab.iMS = ab.iE + (NENT * 64) / 256;
            ab.iEnd = ab.iMS + cdiv(DROWS * 2, 256);
            k_cvt_al2<<<ab.off[3] + ab.iEnd, 256>>>(ab);
        }

        // hs GEMMs (K-resident, both halves)
        {
            GemmBatch hb;
            hb.J = 128; hb.nseg = 6;
            int acc = 0;
            for (int r = 0; r < 6; r++) {
                int st = g_rels[r].stype;
                int Ns = ncnt[st];
                hb.seg[r] = { nullptr, xh + (size_t)toff[st]*64, xl + (size_t)toff[st]*64,
                              W_src + (size_t)(l*6+r)*128*64, nullptr, nullptr,
                              hsb + (size_t)soff[r]*128, Ns, 64, 0 };
                hb.off[r] = acc; acc += cdiv(Ns, 128);
            }
            hb.off[6] = acc;
            k_gemm_hs<<<acc, 256, SMEM_HS>>>(hb);
        }

        // edge passes
        {
            EdgeBatch eb2;
            int accA = 0, accC = 0;
            for (int r = 0; r < 6; r++) {
                eb2.seg[r].src = (const int*)d_in[g_rels[r].sidx];
                eb2.seg[r].dst = (const int*)d_in[g_rels[r].didx];
                eb2.seg[r].e   = ebuf + (size_t)eoff[r]*2;
                eb2.seg[r].als = als + soff[r]*2;
                eb2.seg[r].ald = ald + doff[r]*2;
                eb2.seg[r].s   = sb + doff[r]*2;
                eb2.seg[r].hs  = hsb + (size_t)soff[r]*128;
                eb2.seg[r].nb  = nxt[g_rels[r].dtype];
                eb2.seg[r].E   = E[r];
                eb2.offA[r] = accA; accA += cdiv(E[r], 256);
                eb2.offC[r] = accC; accC += cdiv(E[r] * 8, 256);
            }
            eb2.offA[6] = accA; eb2.offC[6] = accC;
            k_edge_ps<<<accA, 256>>>(eb2);
            k_edge_c_b<<<accC, 256>>>(eb2);
        }

        float* t;
        t = cur[0]; cur[0] = nxt[0]; nxt[0] = t;
        t = cur[1]; cur[1] = nxt[1]; nxt[1] = t;
        t = cur[2]; cur[2] = nxt[2]; nxt[2] = t;
    }

    k_cls<<<cdiv(NPOST, 256), 256>>>(cur[1], cls_w1, cls_b1, cls_w2, cls_b2,
                                     (float*)d_out, NPOST);
}

// round 13
// speedup vs baseline: 1.3173x; 1.3173x over previous
#include <cuda_runtime.h>
#include <cuda_bf16.h>
#include <cuda_fp16.h>
#include <cstdint>
#include <math.h>

#define NUSER 50000
#define NPOST 100000
#define NENT  20000
#define NNODE 170000
#define SROWS 400000      // total hs rows over 6 relations
#define DROWS 420000      // total dst rows over 6 relations
#define ETOT  1550000
#define SCAN_NB 1641      // cdiv(DROWS,256)

static inline int cdiv(int a, int b) { return (a + b - 1) / b; }

// ---------------- static scratch ----------------
__device__ float g_f0_post[NPOST*64];
__device__ float g_f0_user[NUSER*64];
__device__ float g_f0_ent [NENT *64];
__device__ float g_f1_post[NPOST*64];
__device__ float g_f1_user[NUSER*64];
__device__ float g_f1_ent [NENT *64];
__device__ __nv_bfloat16 g_xh[(size_t)NNODE*64];
__device__ __nv_bfloat16 g_xl[(size_t)NNODE*64];
__device__ __half g_hs[(size_t)SROWS*128];
__device__ float g_als[SROWS*2];
__device__ float g_ald[DROWS*2];
__device__ float g_s  [DROWS*2];
__device__ float g_e  [ETOT*2];
__device__ float g_u  [12*256];
// dst-sorted edge arrays (built once)
__device__ int g_cnt[DROWS];
__device__ int g_cur[DROWS];
__device__ int g_bsum[SCAN_NB + 256];
__device__ int g_src_s[ETOT];
__device__ int g_dst_s[ETOT];

// ---------------- helpers ----------------
__device__ __forceinline__ void red_add_v4(float* a, float4 v) {
    asm volatile("red.global.add.v4.f32 [%0], {%1,%2,%3,%4};"
                 :: "l"(a), "f"(v.x), "f"(v.y), "f"(v.z), "f"(v.w) : "memory");
}
__device__ __forceinline__ uint32_t smem_u32(const void* p) {
    return (uint32_t)__cvta_generic_to_shared(p);
}
__device__ __forceinline__ void ldsm_x4(uint32_t& r0, uint32_t& r1, uint32_t& r2,
                                        uint32_t& r3, uint32_t a) {
    asm volatile("ldmatrix.sync.aligned.m8n8.x4.shared.b16 {%0,%1,%2,%3}, [%4];"
                 : "=r"(r0), "=r"(r1), "=r"(r2), "=r"(r3) : "r"(a));
}
__device__ __forceinline__ void mma16816(float* c, const uint32_t* a, const uint32_t* b) {
    asm volatile("mma.sync.aligned.m16n8k16.row.col.f32.bf16.bf16.f32 "
                 "{%0,%1,%2,%3}, {%4,%5,%6,%7}, {%8,%9}, {%0,%1,%2,%3};"
                 : "+f"(c[0]), "+f"(c[1]), "+f"(c[2]), "+f"(c[3])
                 : "r"(a[0]), "r"(a[1]), "r"(a[2]), "r"(a[3]), "r"(b[0]), "r"(b[1]));
}
__device__ __forceinline__ void cvt_store(__nv_bfloat16* ph, __nv_bfloat16* pl, float4 v) {
    float f[4] = { v.x, v.y, v.z, v.w };
    __nv_bfloat162 h2[2], l2[2];
#pragma unroll
    for (int i = 0; i < 2; i++) {
        __nv_bfloat16 h0 = __float2bfloat16_rn(f[2*i]);
        __nv_bfloat16 h1 = __float2bfloat16_rn(f[2*i+1]);
        __nv_bfloat16 l0 = __float2bfloat16_rn(f[2*i]   - __bfloat162float(h0));
        __nv_bfloat16 l1 = __float2bfloat16_rn(f[2*i+1] - __bfloat162float(h1));
        h2[i] = __nv_bfloat162(h0, h1);
        l2[i] = __nv_bfloat162(l0, l1);
    }
    ((__nv_bfloat162*)ph)[0] = h2[0]; ((__nv_bfloat162*)ph)[1] = h2[1];
    ((__nv_bfloat162*)pl)[0] = l2[0]; ((__nv_bfloat162*)pl)[1] = l2[1];
}
__device__ __forceinline__ float leaky(float x) { return x > 0.f ? x : 0.2f * x; }

// ================= batched tensor-core GEMM (bf16 split) =================
#define XS 40

struct GemmSeg { const float* X; const __nv_bfloat16* Xh; const __nv_bfloat16* Xl;
                 const float* W; const float* bias; float* Y; __half* Yh;
                 int N; int K; int relu; };
struct GemmBatch { GemmSeg seg[6]; int off[7]; int nseg; int J; };

template<int PAIR>
__global__ __launch_bounds__(256) void k_gemm_t(GemmBatch gb) {
    int b = blockIdx.x;
    int sg = 0;
    while (sg + 1 < gb.nseg && b >= gb.off[sg + 1]) sg++;
    const GemmSeg G = gb.seg[sg];
    const int row0 = (b - gb.off[sg]) * 128;
    const int j0 = blockIdx.y * 64;
    const int K = G.K, N = G.N, J = gb.J;

    __shared__ __align__(16) __nv_bfloat16 sXh[128*XS];
    __shared__ __align__(16) __nv_bfloat16 sXl[128*XS];
    __shared__ __align__(16) __nv_bfloat16 sWh[64*XS];
    __shared__ __align__(16) __nv_bfloat16 sWl[64*XS];

    const int tid = threadIdx.x;
    const int wid = tid >> 5, lane = tid & 31;
    const int m_base = (wid >> 1) * 32;
    const int n_base = (wid & 1) * 32;

    float acc[2][4][4];
#pragma unroll
    for (int i = 0; i < 2; i++)
#pragma unroll
        for (int j = 0; j < 4; j++)
#pragma unroll
            for (int q = 0; q < 4; q++) acc[i][j][q] = 0.f;

    const int lr = lane & 7, lq = lane >> 3;
    const int a_row = (lq & 1) * 8 + lr;
    const int a_kc  = (lq >> 1) * 8;
    const int b_row = (lq >> 1) * 8 + lr;
    const int b_kc  = (lq & 1) * 8;

    for (int k0 = 0; k0 < K; k0 += 32) {
        if (PAIR) {
#pragma unroll
            for (int q = 0; q < 2; q++) {
                int i = tid + q * 256;
                int r = i >> 2, c8 = (i & 3) * 8;
                int row = row0 + r;
                uint4 vh = make_uint4(0,0,0,0), vl = make_uint4(0,0,0,0);
                if (row < N) {
                    vh = *(const uint4*)&G.Xh[(size_t)row * 64 + k0 + c8];
                    vl = *(const uint4*)&G.Xl[(size_t)row * 64 + k0 + c8];
                }
                *(uint4*)&sXh[r*XS + c8] = vh;
                *(uint4*)&sXl[r*XS + c8] = vl;
            }
        } else {
#pragma unroll
            for (int q = 0; q < 4; q++) {
                int i = tid + q * 256;
                int r = i >> 3, c4 = (i & 7) * 4;
                int row = row0 + r;
                float4 v = make_float4(0.f, 0.f, 0.f, 0.f);
                if (row < N) v = *(const float4*)&G.X[(size_t)row * K + k0 + c4];
                if (G.relu) {
                    v.x = fmaxf(v.x, 0.f); v.y = fmaxf(v.y, 0.f);
                    v.z = fmaxf(v.z, 0.f); v.w = fmaxf(v.w, 0.f);
                }
                cvt_store(&sXh[r*XS + c4], &sXl[r*XS + c4], v);
            }
        }
#pragma unroll
        for (int q = 0; q < 2; q++) {
            int i = tid + q * 256;
            int r = i >> 3, c4 = (i & 7) * 4;
            float4 v = *(const float4*)&G.W[(size_t)(j0 + r) * K + k0 + c4];
            cvt_store(&sWh[r*XS + c4], &sWl[r*XS + c4], v);
        }
        __syncthreads();

#pragma unroll
        for (int kk = 0; kk < 32; kk += 16) {
            uint32_t Ah[2][4], Al[2][4], Bh[4][2], Bl[4][2];
#pragma unroll
            for (int im = 0; im < 2; im++) {
                int r = m_base + im * 16 + a_row;
                ldsm_x4(Ah[im][0], Ah[im][1], Ah[im][2], Ah[im][3],
                        smem_u32(&sXh[r*XS + kk + a_kc]));
                ldsm_x4(Al[im][0], Al[im][1], Al[im][2], Al[im][3],
                        smem_u32(&sXl[r*XS + kk + a_kc]));
            }
#pragma unroll
            for (int nn = 0; nn < 2; nn++) {
                int r = n_base + nn * 16 + b_row;
                uint32_t r0, r1, r2, r3;
                ldsm_x4(r0, r1, r2, r3, smem_u32(&sWh[r*XS + kk + b_kc]));
                Bh[nn*2][0] = r0; Bh[nn*2][1] = r1;
                Bh[nn*2+1][0] = r2; Bh[nn*2+1][1] = r3;
                ldsm_x4(r0, r1, r2, r3, smem_u32(&sWl[r*XS + kk + b_kc]));
                Bl[nn*2][0] = r0; Bl[nn*2][1] = r1;
                Bl[nn*2+1][0] = r2; Bl[nn*2+1][1] = r3;
            }
#pragma unroll
            for (int im = 0; im < 2; im++)
#pragma unroll
                for (int jn = 0; jn < 4; jn++) {
                    mma16816(acc[im][jn], Ah[im], Bh[jn]);
                    mma16816(acc[im][jn], Al[im], Bh[jn]);
                    mma16816(acc[im][jn], Ah[im], Bl[jn]);
                }
        }
        __syncthreads();
    }

    const int r_lo = lane >> 2;
    const int c_lo = (lane & 3) * 2;
#pragma unroll
    for (int im = 0; im < 2; im++) {
#pragma unroll
        for (int jn = 0; jn < 4; jn++) {
            int col = j0 + n_base + jn * 8 + c_lo;
            int row1 = row0 + m_base + im * 16 + r_lo;
            int row2 = row1 + 8;
            if (PAIR) {
                if (row1 < N)
                    *(__half2*)&G.Yh[(size_t)row1 * J + col] =
                        __floats2half2_rn(acc[im][jn][0], acc[im][jn][1]);
                if (row2 < N)
                    *(__half2*)&G.Yh[(size_t)row2 * J + col] =
                        __floats2half2_rn(acc[im][jn][2], acc[im][jn][3]);
            } else {
                float2 bb = make_float2(0.f, 0.f);
                if (G.bias) bb = *(const float2*)&G.bias[col];
                if (row1 < N)
                    *(float2*)&G.Y[(size_t)row1 * J + col] =
                        make_float2(acc[im][jn][0] + bb.x, acc[im][jn][1] + bb.y);
                if (row2 < N)
                    *(float2*)&G.Y[(size_t)row2 * J + col] =
                        make_float2(acc[im][jn][2] + bb.x, acc[im][jn][3] + bb.y);
            }
        }
    }
}

// ================= fold attention vectors =================
__global__ void k_prep_u_all(const float* __restrict__ a_s, const float* __restrict__ a_d,
                             const float* __restrict__ Ws, const float* __restrict__ Wd,
                             float* __restrict__ u) {
    int b = blockIdx.x;
    int t = threadIdx.x;
    int h = t >> 6, k = t & 63;
    const float* as = a_s + b * 128;
    const float* ad = a_d + b * 128;
    const float* ws = Ws + b * 128 * 64;
    const float* wd = Wd + b * 128 * 64;
    float us = 0.f, ud = 0.f;
#pragma unroll 8
    for (int c = 0; c < 64; c++) {
        us += as[h*64 + c] * ws[(h*64 + c)*64 + k];
        ud += ad[h*64 + c] * wd[(h*64 + c)*64 + k];
    }
    u[b*256 + t] = us;
    u[b*256 + 128 + t] = ud;
}

// ================= cvt + al =================
struct AlJob { const float* u; float* out; };
struct AlSeg { const float* x; __nv_bfloat16* xh; __nv_bfloat16* xl;
               int N; int relu; int njobs; AlJob job[6]; };
struct AlBatch { AlSeg seg[3]; int off[4]; };

__global__ __launch_bounds__(256) void k_cvt_al_b(AlBatch ab) {
    int b = blockIdx.x;
    int sg = 0;
    while (sg + 1 < 3 && b >= ab.off[sg + 1]) sg++;
    const AlSeg S = ab.seg[sg];
    __shared__ float su[6*128];
    for (int i = threadIdx.x; i < S.njobs * 128; i += 256)
        su[i] = S.job[i >> 7].u[i & 127];
    __syncthreads();
    int n = (b - ab.off[sg]) * 256 + threadIdx.x;
    if (n >= S.N) return;
    float xr[64];
    const float4* xp = (const float4*)(S.x + (size_t)n * 64);
#pragma unroll
    for (int i = 0; i < 16; i++) {
        float4 v = xp[i];
        if (S.relu) {
            v.x = fmaxf(v.x, 0.f); v.y = fmaxf(v.y, 0.f);
            v.z = fmaxf(v.z, 0.f); v.w = fmaxf(v.w, 0.f);
        }
        xr[i*4] = v.x; xr[i*4+1] = v.y; xr[i*4+2] = v.z; xr[i*4+3] = v.w;
    }
#pragma unroll
    for (int i = 0; i < 8; i++) {
        uint32_t hw[4], lw[4];
#pragma unroll
        for (int j = 0; j < 4; j++) {
            float f0 = xr[i*8 + 2*j], f1 = xr[i*8 + 2*j + 1];
            __nv_bfloat16 h0 = __float2bfloat16_rn(f0);
            __nv_bfloat16 h1 = __float2bfloat16_rn(f1);
            __nv_bfloat16 l0 = __float2bfloat16_rn(f0 - __bfloat162float(h0));
            __nv_bfloat16 l1 = __float2bfloat16_rn(f1 - __bfloat162float(h1));
            __nv_bfloat162 hp(h0, h1), lp(l0, l1);
            hw[j] = *(uint32_t*)&hp; lw[j] = *(uint32_t*)&lp;
        }
        *(uint4*)&S.xh[(size_t)n*64 + i*8] = make_uint4(hw[0], hw[1], hw[2], hw[3]);
        *(uint4*)&S.xl[(size_t)n*64 + i*8] = make_uint4(lw[0], lw[1], lw[2], lw[3]);
    }
    for (int j = 0; j < S.njobs; j++) {
        const float* uu = su + j * 128;
        float d0 = 0.f, d1 = 0.f;
#pragma unroll
        for (int k = 0; k < 64; k++) { d0 += xr[k]*uu[k]; d1 += xr[k]*uu[64+k]; }
        S.job[j].out[n*2] = d0;
        S.job[j].out[n*2+1] = d1;
    }
}

// ================= per-layer init (bias-init nb + s=0) =================
__global__ void k_init_layer(float* __restrict__ nbP, float* __restrict__ nbU,
                             float* __restrict__ nbE,
                             const float* bP0, const float* bP1, const float* bP2,
                             const float* bU0, const float* bU1, const float* bE0,
                             float* __restrict__ s,
                             int oU, int oE, int oMS) {
    int b = blockIdx.x, t = threadIdx.x;
    if (b < oU) {
        int i = b * 256 + t; int c = i & 63;
        nbP[i] = bP0[c] + bP1[c] + bP2[c];
    } else if (b < oE) {
        int i = (b - oU) * 256 + t; int c = i & 63;
        nbU[i] = bU0[c] + bU1[c];
    } else if (b < oMS) {
        int i = (b - oE) * 256 + t; int c = i & 63;
        nbE[i] = bE0[c];
    } else {
        int i = (b - oMS) * 256 + t;
        if (i < DROWS * 2) s[i] = 0.f;
    }
}

// ================= dst-sort build (once) =================
struct BRel { const int* src; const int* dst; int E; int doff; };
struct BCfg { BRel rel[6]; int offE[7]; };

__global__ void k_zero(int* __restrict__ c, int n) {
    int i = blockIdx.x * 256 + threadIdx.x;
    if (i < n) c[i] = 0;
}

__global__ void k_hist(BCfg bc, int* __restrict__ counts) {
    int b = blockIdx.x;
    int sg = 0;
    while (sg + 1 < 6 && b >= bc.offE[sg + 1]) sg++;
    const BRel R = bc.rel[sg];
    int e = (b - bc.offE[sg]) * 256 + threadIdx.x;
    if (e >= R.E) return;
    atomicAdd(&counts[R.doff + R.dst[e]], 1);
}

__global__ void k_scan_block(const int* __restrict__ counts, int* __restrict__ out,
                             int* __restrict__ bsum, int n) {
    __shared__ int sh[256];
    int t = threadIdx.x;
    int i = blockIdx.x * 256 + t;
    int v = (i < n) ? counts[i] : 0;
    sh[t] = v;
    __syncthreads();
#pragma unroll
    for (int off = 1; off < 256; off <<= 1) {
        int tmp = (t >= off) ? sh[t - off] : 0;
        __syncthreads();
        sh[t] += tmp;
        __syncthreads();
    }
    if (i < n) out[i] = sh[t] - v;
    if (t == 255) bsum[blockIdx.x] = sh[255];
}

__global__ void k_scan_bsum(int* __restrict__ bsum, int nb) {
    const int CH = (SCAN_NB + 255) / 256;
    __shared__ int sh[256];
    int t = threadIdx.x;
    int base = t * CH;
    int v[CH];
    int tot = 0;
#pragma unroll
    for (int i = 0; i < CH; i++) {
        int idx = base + i;
        v[i] = (idx < nb) ? bsum[idx] : 0;
        tot += v[i];
    }
    sh[t] = tot;
    __syncthreads();
#pragma unroll
    for (int off = 1; off < 256; off <<= 1) {
        int tmp = (t >= off) ? sh[t - off] : 0;
        __syncthreads();
        sh[t] += tmp;
        __syncthreads();
    }
    int run = sh[t] - tot;
#pragma unroll
    for (int i = 0; i < CH; i++) {
        int idx = base + i;
        if (idx < nb) { bsum[idx] = run; run += v[i]; }
    }
}

__global__ void k_scan_add(int* __restrict__ cur, const int* __restrict__ bsum, int n) {
    int i = blockIdx.x * 256 + threadIdx.x;
    if (i < n) cur[i] += bsum[i >> 8];
}

// scatter: fill dst-sorted src/dst arrays (dst stored local to relation)
__global__ void k_scatter2(BCfg bc, int* __restrict__ cur,
                           int* __restrict__ src_s, int* __restrict__ dst_s) {
    int b = blockIdx.x;
    int sg = 0;
    while (sg + 1 < 6 && b >= bc.offE[sg + 1]) sg++;
    const BRel R = bc.rel[sg];
    int e = (b - bc.offE[sg]) * 256 + threadIdx.x;
    if (e >= R.E) return;
    int d = R.dst[e];
    int pos = atomicAdd(&cur[R.doff + d], 1);
    src_s[pos] = R.src[e];
    dst_s[pos] = d;
}

// ================= batched edge passes (sorted order) =================
struct EdgeSeg {
    const int* src; const int* dst;          // dst-sorted arrays (dst local)
    float* e; const float* als; const float* ald;
    float* s; const __half* hs; float* nb;
    int E;
};
struct EdgeBatch { EdgeSeg seg[6]; int offA[7]; int offC[7]; };

__global__ __launch_bounds__(256) void k_edge_ps(EdgeBatch eb) {
    int b = blockIdx.x;
    int sg = 0;
    while (sg + 1 < 6 && b >= eb.offA[sg + 1]) sg++;
    const EdgeSeg S = eb.seg[sg];
    int e = (b - eb.offA[sg]) * 256 + threadIdx.x;
    if (e >= S.E) return;
    int sN = S.src[e], dN = S.dst[e];
    float2 a  = ((const float2*)S.als)[sN];
    float2 bb = ((const float2*)S.ald)[dN];
    float p0 = __expf(leaky(a.x + bb.x) - 10.f);
    float p1 = __expf(leaky(a.y + bb.y) - 10.f);
    ((float2*)S.e)[e] = make_float2(p0, p1);
    atomicAdd(&S.s[dN*2],     p0);
    atomicAdd(&S.s[dN*2 + 1], p1);
}

__global__ __launch_bounds__(256) void k_edge_c_b(EdgeBatch eb) {
    int b = blockIdx.x;
    int sg = 0;
    while (sg + 1 < 6 && b >= eb.offC[sg + 1]) sg++;
    const EdgeSeg S = eb.seg[sg];
    int t = (b - eb.offC[sg]) * 256 + threadIdx.x;
    int e = t >> 3, lane = t & 7;
    if (e >= S.E) return;
    int sN = S.src[e], dN = S.dst[e];
    float2 p  = ((const float2*)S.e)[e];
    float2 ss = ((const float2*)S.s)[dN];
    float a0 = 0.5f * p.x / (ss.x + 1e-16f);
    float a1 = 0.5f * p.y / (ss.y + 1e-16f);
    const __half* hr = S.hs + (size_t)sN * 128;
    int c0 = lane * 8;
    uint4 u0 = *(const uint4*)&hr[c0];
    uint4 u1 = *(const uint4*)&hr[64 + c0];
    const __half2* h0 = (const __half2*)&u0;
    const __half2* h1 = (const __half2*)&u1;
    float o[8];
#pragma unroll
    for (int j = 0; j < 4; j++) {
        float2 f0 = __half22float2(h0[j]);
        float2 f1 = __half22float2(h1[j]);
        o[2*j]   = a0*f0.x + a1*f1.x;
        o[2*j+1] = a0*f0.y + a1*f1.y;
    }
    float* base = S.nb + (size_t)dN * 64 + c0;
    red_add_v4(base,     make_float4(o[0], o[1], o[2], o[3]));
    red_add_v4(base + 4, make_float4(o[4], o[5], o[6], o[7]));
}

// ================= fused classifier =================
__global__ __launch_bounds__(256) void k_cls(const float* __restrict__ hp,
                      const float* __restrict__ w1, const float* __restrict__ b1,
                      const float* __restrict__ w2, const float* __restrict__ b2,
                      float* __restrict__ out, int N) {
    __shared__ float sw1[32*64];
    __shared__ float sb1[32];
    __shared__ float sw2[32];
    __shared__ float sb2;
    for (int i = threadIdx.x; i < 2048; i += blockDim.x) sw1[i] = w1[i];
    if (threadIdx.x < 32) { sb1[threadIdx.x] = b1[threadIdx.x]; sw2[threadIdx.x] = w2[threadIdx.x]; }
    if (threadIdx.x == 0) sb2 = b2[0];
    __syncthreads();
    int n = blockIdx.x * blockDim.x + threadIdx.x;
    if (n >= N) return;
    float xr[64];
    const float4* xp = (const float4*)(hp + (size_t)n*64);
#pragma unroll
    for (int i = 0; i < 16; i++) {
        float4 v = xp[i];
        xr[i*4]   = fmaxf(v.x, 0.f); xr[i*4+1] = fmaxf(v.y, 0.f);
        xr[i*4+2] = fmaxf(v.z, 0.f); xr[i*4+3] = fmaxf(v.w, 0.f);
    }
    float o = sb2;
#pragma unroll 4
    for (int j = 0; j < 32; j++) {
        float acc = sb1[j];
#pragma unroll
        for (int k = 0; k < 64; k++) acc += xr[k] * sw1[j*64 + k];
        o += fmaxf(acc, 0.f) * sw2[j];
    }
    out[n] = o;
}

// ================= host orchestration =================
struct RelCfg { int sidx, didx, stype, dtype; };
static const RelCfg g_rels[6] = {
    {3, 4,  0, 1},   // publish  user->post
    {5, 6,  0, 1},   // repost   user->post
    {7, 8,  1, 2},   // contain  post->ent
    {9, 10, 0, 0},   // interact user->user
    {11,12, 0, 0},   // follow   user->user
    {13,14, 1, 1},   // similar  post->post
};

extern "C" void kernel_launch(void* const* d_in, const int* in_sizes, int n_in,
                              void* d_out, int out_size)
{
    const float* x_post = (const float*)d_in[0];
    const float* x_user = (const float*)d_in[1];
    const float* x_ent  = (const float*)d_in[2];
    const float* post_w = (const float*)d_in[15];
    const float* post_b = (const float*)d_in[16];
    const float* user_w = (const float*)d_in[17];
    const float* user_b = (const float*)d_in[18];
    const float* ent_w  = (const float*)d_in[19];
    const float* ent_b  = (const float*)d_in[20];
    const float* W_src  = (const float*)d_in[21];
    const float* W_dstP = (const float*)d_in[22];
    const float* a_srcP = (const float*)d_in[23];
    const float* a_dstP = (const float*)d_in[24];
    const float* gat_b  = (const float*)d_in[25];
    const float* cls_w1 = (const float*)d_in[26];
    const float* cls_b1 = (const float*)d_in[27];
    const float* cls_w2 = (const float*)d_in[28];
    const float* cls_b2 = (const float*)d_in[29];

    float *f0p,*f0u,*f0e,*f1p,*f1u,*f1e,*als,*ald,*sb,*ebuf,*ub;
    __nv_bfloat16 *xh, *xl;
    __half* hsb;
    int *cnt, *curp, *bsum, *src_s, *dst_s;
    cudaGetSymbolAddress((void**)&f0p, g_f0_post);
    cudaGetSymbolAddress((void**)&f0u, g_f0_user);
    cudaGetSymbolAddress((void**)&f0e, g_f0_ent);
    cudaGetSymbolAddress((void**)&f1p, g_f1_post);
    cudaGetSymbolAddress((void**)&f1u, g_f1_user);
    cudaGetSymbolAddress((void**)&f1e, g_f1_ent);
    cudaGetSymbolAddress((void**)&xh,  g_xh);
    cudaGetSymbolAddress((void**)&xl,  g_xl);
    cudaGetSymbolAddress((void**)&hsb, g_hs);
    cudaGetSymbolAddress((void**)&als, g_als);
    cudaGetSymbolAddress((void**)&ald, g_ald);
    cudaGetSymbolAddress((void**)&sb,  g_s);
    cudaGetSymbolAddress((void**)&ebuf,g_e);
    cudaGetSymbolAddress((void**)&ub,  g_u);
    cudaGetSymbolAddress((void**)&cnt, g_cnt);
    cudaGetSymbolAddress((void**)&curp, g_cur);
    cudaGetSymbolAddress((void**)&bsum, g_bsum);
    cudaGetSymbolAddress((void**)&src_s, g_src_s);
    cudaGetSymbolAddress((void**)&dst_s, g_dst_s);

    const int ncnt[3] = { NUSER, NPOST, NENT };
    const int toff[3] = { 0, NUSER, NUSER + NPOST };

    int E[6], soff[6], doff[6], eoff[6];
    int sacc = 0, dacc = 0, eacc = 0;
    for (int r = 0; r < 6; r++) {
        E[r] = in_sizes[g_rels[r].sidx];
        soff[r] = sacc; sacc += ncnt[g_rels[r].stype];
        doff[r] = dacc; dacc += ncnt[g_rels[r].dtype];
        eoff[r] = eacc; eacc += E[r];
    }

    // ---- dst-sort edges (once; shared by both layers) ----
    {
        BCfg bc;
        int acc = 0;
        for (int r = 0; r < 6; r++) {
            bc.rel[r].src = (const int*)d_in[g_rels[r].sidx];
            bc.rel[r].dst = (const int*)d_in[g_rels[r].didx];
            bc.rel[r].E = E[r];
            bc.rel[r].doff = doff[r];
            bc.offE[r] = acc; acc += cdiv(E[r], 256);
        }
        bc.offE[6] = acc;
        k_zero<<<cdiv(DROWS, 256), 256>>>(cnt, DROWS);
        k_hist<<<acc, 256>>>(bc, cnt);
        k_scan_block<<<SCAN_NB, 256>>>(cnt, curp, bsum, DROWS);
        k_scan_bsum<<<1, 256>>>(bsum, SCAN_NB);
        k_scan_add<<<cdiv(DROWS, 256), 256>>>(curp, bsum, DROWS);
        k_scatter2<<<acc, 256>>>(bc, curp, src_s, dst_s);
    }

    // fold attention vectors
    k_prep_u_all<<<12, 128>>>(a_srcP, a_dstP, W_src, W_dstP, ub);

    // input projections
    {
        GemmBatch pb;
        pb.J = 64; pb.nseg = 3;
        pb.seg[0] = { x_post, nullptr, nullptr, post_w, post_b, f0p, nullptr, NPOST, 768, 0 };
        pb.seg[1] = { x_user, nullptr, nullptr, user_w, user_b, f0u, nullptr, NUSER, 32, 0 };
        pb.seg[2] = { x_ent,  nullptr, nullptr, ent_w,  ent_b,  f0e, nullptr, NENT,  64, 0 };
        pb.off[0] = 0;
        pb.off[1] = pb.off[0] + cdiv(NPOST, 128);
        pb.off[2] = pb.off[1] + cdiv(NUSER, 128);
        pb.off[3] = pb.off[2] + cdiv(NENT, 128);
        k_gemm_t<0><<<dim3(pb.off[3], 1), 256>>>(pb);
    }

    float* cur[3] = { f0u, f0p, f0e };
    float* nxt[3] = { f1u, f1p, f1e };

    for (int l = 0; l < 2; l++) {
        int relu = (l == 1);

        {
            int oU  = (NPOST * 64) / 256;
            int oE  = oU + (NUSER * 64) / 256;
            int oMS = oE + (NENT * 64) / 256;
            int tot = oMS + cdiv(DROWS * 2, 256);
            k_init_layer<<<tot, 256>>>(nxt[1], nxt[0], nxt[2],
                gat_b + (l*6+0)*64, gat_b + (l*6+1)*64, gat_b + (l*6+5)*64,
                gat_b + (l*6+3)*64, gat_b + (l*6+4)*64, gat_b + (l*6+2)*64,
                sb, oU, oE, oMS);
        }

        {
            AlBatch ab;
            ab.seg[0].x = cur[0]; ab.seg[0].xh = xh + (size_t)toff[0]*64;
            ab.seg[0].xl = xl + (size_t)toff[0]*64;
            ab.seg[0].N = NUSER; ab.seg[0].relu = relu; ab.seg[0].njobs = 6;
            ab.seg[0].job[0] = { ub + (l*6+0)*256,       als + soff[0]*2 };
            ab.seg[0].job[1] = { ub + (l*6+1)*256,       als + soff[1]*2 };
            ab.seg[0].job[2] = { ub + (l*6+3)*256,       als + soff[3]*2 };
            ab.seg[0].job[3] = { ub + (l*6+3)*256 + 128, ald + doff[3]*2 };
            ab.seg[0].job[4] = { ub + (l*6+4)*256,       als + soff[4]*2 };
            ab.seg[0].job[5] = { ub + (l*6+4)*256 + 128, ald + doff[4]*2 };
            ab.seg[1].x = cur[1]; ab.seg[1].xh = xh + (size_t)toff[1]*64;
            ab.seg[1].xl = xl + (size_t)toff[1]*64;
            ab.seg[1].N = NPOST; ab.seg[1].relu = relu; ab.seg[1].njobs = 5;
            ab.seg[1].job[0] = { ub + (l*6+0)*256 + 128, ald + doff[0]*2 };
            ab.seg[1].job[1] = { ub + (l*6+1)*256 + 128, ald + doff[1]*2 };
            ab.seg[1].job[2] = { ub + (l*6+2)*256,       als + soff[2]*2 };
            ab.seg[1].job[3] = { ub + (l*6+5)*256,       als + soff[5]*2 };
            ab.seg[1].job[4] = { ub + (l*6+5)*256 + 128, ald + doff[5]*2 };
            ab.seg[1].job[5] = { nullptr, nullptr };
            ab.seg[2].x = cur[2]; ab.seg[2].xh = xh + (size_t)toff[2]*64;
            ab.seg[2].xl = xl + (size_t)toff[2]*64;
            ab.seg[2].N = NENT; ab.seg[2].relu = relu; ab.seg[2].njobs = 1;
            ab.seg[2].job[0] = { ub + (l*6+2)*256 + 128, ald + doff[2]*2 };
            for (int j = 1; j < 6; j++) ab.seg[2].job[j] = { nullptr, nullptr };
            ab.off[0] = 0;
            ab.off[1] = ab.off[0] + cdiv(NUSER, 256);
            ab.off[2] = ab.off[1] + cdiv(NPOST, 256);
            ab.off[3] = ab.off[2] + cdiv(NENT, 256);
            k_cvt_al_b<<<ab.off[3], 256>>>(ab);
        }

        {
            GemmBatch hb;
            hb.J = 128; hb.nseg = 6;
            int acc = 0;
            for (int r = 0; r < 6; r++) {
                int st = g_rels[r].stype;
                int Ns = ncnt[st];
                hb.seg[r] = { nullptr, xh + (size_t)toff[st]*64, xl + (size_t)toff[st]*64,
                              W_src + (size_t)(l*6+r)*128*64, nullptr, nullptr,
                              hsb + (size_t)soff[r]*128, Ns, 64, 0 };
                hb.off[r] = acc; acc += cdiv(Ns, 128);
            }
            hb.off[6] = acc;
            k_gemm_t<1><<<dim3(acc, 2), 256>>>(hb);
        }

        {
            EdgeBatch eb2;
            int accA = 0, accC = 0;
            for (int r = 0; r < 6; r++) {
                eb2.seg[r].src = src_s + eoff[r];
                eb2.seg[r].dst = dst_s + eoff[r];
                eb2.seg[r].e   = ebuf + (size_t)eoff[r]*2;
                eb2.seg[r].als = als + soff[r]*2;
                eb2.seg[r].ald = ald + doff[r]*2;
                eb2.seg[r].s   = sb + doff[r]*2;
                eb2.seg[r].hs  = hsb + (size_t)soff[r]*128;
                eb2.seg[r].nb  = nxt[g_rels[r].dtype];
                eb2.seg[r].E   = E[r];
                eb2.offA[r] = accA; accA += cdiv(E[r], 256);
                eb2.offC[r] = accC; accC += cdiv(E[r] * 8, 256);
            }
            eb2.offA[6] = accA; eb2.offC[6] = accC;
            k_edge_ps<<<accA, 256>>>(eb2);
            k_edge_c_b<<<accC, 256>>>(eb2);
        }

        float* t;
        t = cur[0]; cur[0] = nxt[0]; nxt[0] = t;
        t = cur[1]; cur[1] = nxt[1]; nxt[1] = t;
        t = cur[2]; cur[2] = nxt[2]; nxt[2] = t;
    }

    k_cls<<<cdiv(NPOST, 256), 256>>>(cur[1], cls_w1, cls_b1, cls_w2, cls_b2,
                                     (float*)d_out, NPOST);
}

// round 14
// speedup vs baseline: 1.4064x; 1.0676x over previous
#include <cuda_runtime.h>
#include <cuda_bf16.h>
#include <cuda_fp16.h>
#include <cstdint>
#include <math.h>

#define NUSER 50000
#define NPOST 100000
#define NENT  20000
#define NNODE 170000
#define SROWS 400000      // total hs rows over 6 relations
#define DROWS 420000      // total dst rows over 6 relations
#define ETOT  1550000

static inline int cdiv(int a, int b) { return (a + b - 1) / b; }

// ---------------- static scratch ----------------
__device__ float g_f0_post[NPOST*64];
__device__ float g_f0_user[NUSER*64];
__device__ float g_f0_ent [NENT *64];
__device__ float g_f1_post[NPOST*64];
__device__ float g_f1_user[NUSER*64];
__device__ float g_f1_ent [NENT *64];
__device__ __nv_bfloat16 g_xh[(size_t)NNODE*64];
__device__ __nv_bfloat16 g_xl[(size_t)NNODE*64];
__device__ __half g_hs[(size_t)SROWS*128];
__device__ float g_als[SROWS*2];
__device__ float g_ald[DROWS*2];
__device__ float g_s  [DROWS*2];
__device__ float g_e  [ETOT*2];
__device__ float g_u  [12*256];

// ---------------- helpers ----------------
__device__ __forceinline__ void red_add_v4(float* a, float4 v) {
    asm volatile("red.global.add.v4.f32 [%0], {%1,%2,%3,%4};"
                 :: "l"(a), "f"(v.x), "f"(v.y), "f"(v.z), "f"(v.w) : "memory");
}
__device__ __forceinline__ uint32_t smem_u32(const void* p) {
    return (uint32_t)__cvta_generic_to_shared(p);
}
__device__ __forceinline__ void ldsm_x4(uint32_t& r0, uint32_t& r1, uint32_t& r2,
                                        uint32_t& r3, uint32_t a) {
    asm volatile("ldmatrix.sync.aligned.m8n8.x4.shared.b16 {%0,%1,%2,%3}, [%4];"
                 : "=r"(r0), "=r"(r1), "=r"(r2), "=r"(r3) : "r"(a));
}
__device__ __forceinline__ void mma16816(float* c, const uint32_t* a, const uint32_t* b) {
    asm volatile("mma.sync.aligned.m16n8k16.row.col.f32.bf16.bf16.f32 "
                 "{%0,%1,%2,%3}, {%4,%5,%6,%7}, {%8,%9}, {%0,%1,%2,%3};"
                 : "+f"(c[0]), "+f"(c[1]), "+f"(c[2]), "+f"(c[3])
                 : "r"(a[0]), "r"(a[1]), "r"(a[2]), "r"(a[3]), "r"(b[0]), "r"(b[1]));
}
__device__ __forceinline__ void cvt_store(__nv_bfloat16* ph, __nv_bfloat16* pl, float4 v) {
    float f[4] = { v.x, v.y, v.z, v.w };
    __nv_bfloat162 h2[2], l2[2];
#pragma unroll
    for (int i = 0; i < 2; i++) {
        __nv_bfloat16 h0 = __float2bfloat16_rn(f[2*i]);
        __nv_bfloat16 h1 = __float2bfloat16_rn(f[2*i+1]);
        __nv_bfloat16 l0 = __float2bfloat16_rn(f[2*i]   - __bfloat162float(h0));
        __nv_bfloat16 l1 = __float2bfloat16_rn(f[2*i+1] - __bfloat162float(h1));
        h2[i] = __nv_bfloat162(h0, h1);
        l2[i] = __nv_bfloat162(l0, l1);
    }
    ((__nv_bfloat162*)ph)[0] = h2[0]; ((__nv_bfloat162*)ph)[1] = h2[1];
    ((__nv_bfloat162*)pl)[0] = l2[0]; ((__nv_bfloat162*)pl)[1] = l2[1];
}
__device__ __forceinline__ float leaky(float x) { return x > 0.f ? x : 0.2f * x; }

// ================= batched tensor-core GEMM (bf16 split) =================
#define XS 40

struct GemmSeg { const float* X; const __nv_bfloat16* Xh; const __nv_bfloat16* Xl;
                 const float* W; const float* bias; float* Y; __half* Yh;
                 int N; int K; int relu; };
struct GemmBatch { GemmSeg seg[6]; int off[7]; int nseg; int J; };

template<int PAIR>
__global__ __launch_bounds__(256) void k_gemm_t(GemmBatch gb) {
    int b = blockIdx.x;
    int sg = 0;
    while (sg + 1 < gb.nseg && b >= gb.off[sg + 1]) sg++;
    const GemmSeg G = gb.seg[sg];
    const int row0 = (b - gb.off[sg]) * 128;
    const int j0 = blockIdx.y * 64;
    const int K = G.K, N = G.N, J = gb.J;

    __shared__ __align__(16) __nv_bfloat16 sXh[128*XS];
    __shared__ __align__(16) __nv_bfloat16 sXl[128*XS];
    __shared__ __align__(16) __nv_bfloat16 sWh[64*XS];
    __shared__ __align__(16) __nv_bfloat16 sWl[64*XS];

    const int tid = threadIdx.x;
    const int wid = tid >> 5, lane = tid & 31;
    const int m_base = (wid >> 1) * 32;
    const int n_base = (wid & 1) * 32;

    float acc[2][4][4];
#pragma unroll
    for (int i = 0; i < 2; i++)
#pragma unroll
        for (int j = 0; j < 4; j++)
#pragma unroll
            for (int q = 0; q < 4; q++) acc[i][j][q] = 0.f;

    const int lr = lane & 7, lq = lane >> 3;
    const int a_row = (lq & 1) * 8 + lr;
    const int a_kc  = (lq >> 1) * 8;
    const int b_row = (lq >> 1) * 8 + lr;
    const int b_kc  = (lq & 1) * 8;

    for (int k0 = 0; k0 < K; k0 += 32) {
        if (PAIR) {
#pragma unroll
            for (int q = 0; q < 2; q++) {
                int i = tid + q * 256;
                int r = i >> 2, c8 = (i & 3) * 8;
                int row = row0 + r;
                uint4 vh = make_uint4(0,0,0,0), vl = make_uint4(0,0,0,0);
                if (row < N) {
                    vh = *(const uint4*)&G.Xh[(size_t)row * 64 + k0 + c8];
                    vl = *(const uint4*)&G.Xl[(size_t)row * 64 + k0 + c8];
                }
                *(uint4*)&sXh[r*XS + c8] = vh;
                *(uint4*)&sXl[r*XS + c8] = vl;
            }
        } else {
#pragma unroll
            for (int q = 0; q < 4; q++) {
                int i = tid + q * 256;
                int r = i >> 3, c4 = (i & 7) * 4;
                int row = row0 + r;
                float4 v = make_float4(0.f, 0.f, 0.f, 0.f);
                if (row < N) v = *(const float4*)&G.X[(size_t)row * K + k0 + c4];
                if (G.relu) {
                    v.x = fmaxf(v.x, 0.f); v.y = fmaxf(v.y, 0.f);
                    v.z = fmaxf(v.z, 0.f); v.w = fmaxf(v.w, 0.f);
                }
                cvt_store(&sXh[r*XS + c4], &sXl[r*XS + c4], v);
            }
        }
#pragma unroll
        for (int q = 0; q < 2; q++) {
            int i = tid + q * 256;
            int r = i >> 3, c4 = (i & 7) * 4;
            float4 v = *(const float4*)&G.W[(size_t)(j0 + r) * K + k0 + c4];
            cvt_store(&sWh[r*XS + c4], &sWl[r*XS + c4], v);
        }
        __syncthreads();

#pragma unroll
        for (int kk = 0; kk < 32; kk += 16) {
            uint32_t Ah[2][4], Al[2][4], Bh[4][2], Bl[4][2];
#pragma unroll
            for (int im = 0; im < 2; im++) {
                int r = m_base + im * 16 + a_row;
                ldsm_x4(Ah[im][0], Ah[im][1], Ah[im][2], Ah[im][3],
                        smem_u32(&sXh[r*XS + kk + a_kc]));
                ldsm_x4(Al[im][0], Al[im][1], Al[im][2], Al[im][3],
                        smem_u32(&sXl[r*XS + kk + a_kc]));
            }
#pragma unroll
            for (int nn = 0; nn < 2; nn++) {
                int r = n_base + nn * 16 + b_row;
                uint32_t r0, r1, r2, r3;
                ldsm_x4(r0, r1, r2, r3, smem_u32(&sWh[r*XS + kk + b_kc]));
                Bh[nn*2][0] = r0; Bh[nn*2][1] = r1;
                Bh[nn*2+1][0] = r2; Bh[nn*2+1][1] = r3;
                ldsm_x4(r0, r1, r2, r3, smem_u32(&sWl[r*XS + kk + b_kc]));
                Bl[nn*2][0] = r0; Bl[nn*2][1] = r1;
                Bl[nn*2+1][0] = r2; Bl[nn*2+1][1] = r3;
            }
#pragma unroll
            for (int im = 0; im < 2; im++)
#pragma unroll
                for (int jn = 0; jn < 4; jn++) {
                    mma16816(acc[im][jn], Ah[im], Bh[jn]);
                    mma16816(acc[im][jn], Al[im], Bh[jn]);
                    mma16816(acc[im][jn], Ah[im], Bl[jn]);
                }
        }
        __syncthreads();
    }

    const int r_lo = lane >> 2;
    const int c_lo = (lane & 3) * 2;
#pragma unroll
    for (int im = 0; im < 2; im++) {
#pragma unroll
        for (int jn = 0; jn < 4; jn++) {
            int col = j0 + n_base + jn * 8 + c_lo;
            int row1 = row0 + m_base + im * 16 + r_lo;
            int row2 = row1 + 8;
            if (PAIR) {
                if (row1 < N)
                    *(__half2*)&G.Yh[(size_t)row1 * J + col] =
                        __floats2half2_rn(acc[im][jn][0], acc[im][jn][1]);
                if (row2 < N)
                    *(__half2*)&G.Yh[(size_t)row2 * J + col] =
                        __floats2half2_rn(acc[im][jn][2], acc[im][jn][3]);
            } else {
                float2 bb = make_float2(0.f, 0.f);
                if (G.bias) bb = *(const float2*)&G.bias[col];
                if (row1 < N)
                    *(float2*)&G.Y[(size_t)row1 * J + col] =
                        make_float2(acc[im][jn][0] + bb.x, acc[im][jn][1] + bb.y);
                if (row2 < N)
                    *(float2*)&G.Y[(size_t)row2 * J + col] =
                        make_float2(acc[im][jn][2] + bb.x, acc[im][jn][3] + bb.y);
            }
        }
    }
}

// ================= fold attention vectors =================
__global__ void k_prep_u_all(const float* __restrict__ a_s, const float* __restrict__ a_d,
                             const float* __restrict__ Ws, const float* __restrict__ Wd,
                             float* __restrict__ u) {
    int b = blockIdx.x;
    int t = threadIdx.x;
    int h = t >> 6, k = t & 63;
    const float* as = a_s + b * 128;
    const float* ad = a_d + b * 128;
    const float* ws = Ws + b * 128 * 64;
    const float* wd = Wd + b * 128 * 64;
    float us = 0.f, ud = 0.f;
#pragma unroll 8
    for (int c = 0; c < 64; c++) {
        us += as[h*64 + c] * ws[(h*64 + c)*64 + k];
        ud += ad[h*64 + c] * wd[(h*64 + c)*64 + k];
    }
    u[b*256 + t] = us;
    u[b*256 + 128 + t] = ud;
}

// ===== cvt + al (2 threads/row) with fused layer-init blocks =====
struct AlJob { const float* u; float* out; };
struct AlSeg { const float* x; __nv_bfloat16* xh; __nv_bfloat16* xl;
               int N; int relu; int njobs; AlJob job[6]; };
struct AlBatch {
    AlSeg seg[3]; int off[4];
    float *nbP, *nbU, *nbE, *s;
    const float *bP0, *bP1, *bP2, *bU0, *bU1, *bE0;
    int iU, iE, iMS;
};

__global__ __launch_bounds__(256) void k_cvt_al_b(AlBatch ab) {
    int b = blockIdx.x;
    if (b >= ab.off[3]) {
        // ---- fused init region ----
        int b2 = b - ab.off[3];
        int t = threadIdx.x;
        if (b2 < ab.iU) {
            int i = b2 * 256 + t; int c = i & 63;
            ab.nbP[i] = ab.bP0[c] + ab.bP1[c] + ab.bP2[c];
        } else if (b2 < ab.iE) {
            int i = (b2 - ab.iU) * 256 + t; int c = i & 63;
            ab.nbU[i] = ab.bU0[c] + ab.bU1[c];
        } else if (b2 < ab.iMS) {
            int i = (b2 - ab.iE) * 256 + t; int c = i & 63;
            ab.nbE[i] = ab.bE0[c];
        } else {
            int i = (b2 - ab.iMS) * 256 + t;
            if (i < DROWS * 2) ab.s[i] = 0.f;
        }
        return;
    }
    int sg = 0;
    while (sg + 1 < 3 && b >= ab.off[sg + 1]) sg++;
    const AlSeg S = ab.seg[sg];
    __shared__ float su[6*128];
    for (int i = threadIdx.x; i < S.njobs * 128; i += 256)
        su[i] = S.job[i >> 7].u[i & 127];
    __syncthreads();
    int t = threadIdx.x;
    int rowIdx = (b - ab.off[sg]) * 128 + (t >> 1);
    int sub = t & 1;
    int n = min(rowIdx, S.N - 1);          // clamp: keep all lanes active
    int c0 = sub * 32;
    float xr[32];
    const float4* xp = (const float4*)(S.x + (size_t)n * 64 + c0);
#pragma unroll
    for (int i = 0; i < 8; i++) {
        float4 v = xp[i];
        if (S.relu) {
            v.x = fmaxf(v.x, 0.f); v.y = fmaxf(v.y, 0.f);
            v.z = fmaxf(v.z, 0.f); v.w = fmaxf(v.w, 0.f);
        }
        xr[i*4] = v.x; xr[i*4+1] = v.y; xr[i*4+2] = v.z; xr[i*4+3] = v.w;
    }
    // bf16 hi/lo: 32 cols -> 4 x uint4 (h) + 4 x uint4 (l)
#pragma unroll
    for (int i = 0; i < 4; i++) {
        uint32_t hw[4], lw[4];
#pragma unroll
        for (int j = 0; j < 4; j++) {
            float f0 = xr[i*8 + 2*j], f1 = xr[i*8 + 2*j + 1];
            __nv_bfloat16 h0 = __float2bfloat16_rn(f0);
            __nv_bfloat16 h1 = __float2bfloat16_rn(f1);
            __nv_bfloat16 l0 = __float2bfloat16_rn(f0 - __bfloat162float(h0));
            __nv_bfloat16 l1 = __float2bfloat16_rn(f1 - __bfloat162float(h1));
            __nv_bfloat162 hp(h0, h1), lp(l0, l1);
            hw[j] = *(uint32_t*)&hp; lw[j] = *(uint32_t*)&lp;
        }
        if (rowIdx < S.N) {
            *(uint4*)&S.xh[(size_t)n*64 + c0 + i*8] = make_uint4(hw[0], hw[1], hw[2], hw[3]);
            *(uint4*)&S.xl[(size_t)n*64 + c0 + i*8] = make_uint4(lw[0], lw[1], lw[2], lw[3]);
        }
    }
    for (int j = 0; j < S.njobs; j++) {
        const float* uu = su + j * 128;
        float d0 = 0.f, d1 = 0.f;
#pragma unroll
        for (int k = 0; k < 32; k++) {
            d0 += xr[k] * uu[c0 + k];
            d1 += xr[k] * uu[64 + c0 + k];
        }
        d0 += __shfl_xor_sync(0xFFFFFFFFu, d0, 1);
        d1 += __shfl_xor_sync(0xFFFFFFFFu, d1, 1);
        if (sub == 0 && rowIdx < S.N)
            *(float2*)&S.job[j].out[(size_t)rowIdx * 2] = make_float2(d0, d1);
    }
}

// ================= batched edge passes =================
struct EdgeSeg {
    const int* src; const int* dst;
    float* e; const float* als; const float* ald;
    float* s; const __half* hs; float* nb;
    int E;
};
struct EdgeBatch { EdgeSeg seg[6]; int offA[7]; int offC[7]; };

__global__ __launch_bounds__(256) void k_edge_ps(EdgeBatch eb) {
    int b = blockIdx.x;
    int sg = 0;
    while (sg + 1 < 6 && b >= eb.offA[sg + 1]) sg++;
    const EdgeSeg S = eb.seg[sg];
    int e = (b - eb.offA[sg]) * 256 + threadIdx.x;
    if (e >= S.E) return;
    int sN = S.src[e], dN = S.dst[e];
    float2 a  = ((const float2*)S.als)[sN];
    float2 bb = ((const float2*)S.ald)[dN];
    float p0 = __expf(leaky(a.x + bb.x) - 10.f);
    float p1 = __expf(leaky(a.y + bb.y) - 10.f);
    ((float2*)S.e)[e] = make_float2(p0, p1);
    atomicAdd(&S.s[dN*2],     p0);
    atomicAdd(&S.s[dN*2 + 1], p1);
}

__global__ __launch_bounds__(256) void k_edge_c_b(EdgeBatch eb) {
    int b = blockIdx.x;
    int sg = 0;
    while (sg + 1 < 6 && b >= eb.offC[sg + 1]) sg++;
    const EdgeSeg S = eb.seg[sg];
    int t = (b - eb.offC[sg]) * 256 + threadIdx.x;
    int e = t >> 3, lane = t & 7;
    if (e >= S.E) return;
    int sN = S.src[e], dN = S.dst[e];
    float2 p  = ((const float2*)S.e)[e];
    float2 ss = ((const float2*)S.s)[dN];
    float a0 = 0.5f * p.x / (ss.x + 1e-16f);
    float a1 = 0.5f * p.y / (ss.y + 1e-16f);
    const __half* hr = S.hs + (size_t)sN * 128;
    int c0 = lane * 8;
    uint4 u0 = *(const uint4*)&hr[c0];
    uint4 u1 = *(const uint4*)&hr[64 + c0];
    const __half2* h0 = (const __half2*)&u0;
    const __half2* h1 = (const __half2*)&u1;
    float o[8];
#pragma unroll
    for (int j = 0; j < 4; j++) {
        float2 f0 = __half22float2(h0[j]);
        float2 f1 = __half22float2(h1[j]);
        o[2*j]   = a0*f0.x + a1*f1.x;
        o[2*j+1] = a0*f0.y + a1*f1.y;
    }
    float* base = S.nb + (size_t)dN * 64 + c0;
    red_add_v4(base,     make_float4(o[0], o[1], o[2], o[3]));
    red_add_v4(base + 4, make_float4(o[4], o[5], o[6], o[7]));
}

// ================= fused classifier =================
__global__ __launch_bounds__(256) void k_cls(const float* __restrict__ hp,
                      const float* __restrict__ w1, const float* __restrict__ b1,
                      const float* __restrict__ w2, const float* __restrict__ b2,
                      float* __restrict__ out, int N) {
    __shared__ float sw1[32*64];
    __shared__ float sb1[32];
    __shared__ float sw2[32];
    __shared__ float sb2;
    for (int i = threadIdx.x; i < 2048; i += blockDim.x) sw1[i] = w1[i];
    if (threadIdx.x < 32) { sb1[threadIdx.x] = b1[threadIdx.x]; sw2[threadIdx.x] = w2[threadIdx.x]; }
    if (threadIdx.x == 0) sb2 = b2[0];
    __syncthreads();
    int n = blockIdx.x * blockDim.x + threadIdx.x;
    if (n >= N) return;
    float xr[64];
    const float4* xp = (const float4*)(hp + (size_t)n*64);
#pragma unroll
    for (int i = 0; i < 16; i++) {
        float4 v = xp[i];
        xr[i*4]   = fmaxf(v.x, 0.f); xr[i*4+1] = fmaxf(v.y, 0.f);
        xr[i*4+2] = fmaxf(v.z, 0.f); xr[i*4+3] = fmaxf(v.w, 0.f);
    }
    float o = sb2;
#pragma unroll 4
    for (int j = 0; j < 32; j++) {
        float acc = sb1[j];
#pragma unroll
        for (int k = 0; k < 64; k++) acc += xr[k] * sw1[j*64 + k];
        o += fmaxf(acc, 0.f) * sw2[j];
    }
    out[n] = o;
}

// ================= host orchestration =================
struct RelCfg { int sidx, didx, stype, dtype; };
static const RelCfg g_rels[6] = {
    {3, 4,  0, 1},   // publish  user->post
    {5, 6,  0, 1},   // repost   user->post
    {7, 8,  1, 2},   // contain  post->ent
    {9, 10, 0, 0},   // interact user->user
    {11,12, 0, 0},   // follow   user->user
    {13,14, 1, 1},   // similar  post->post
};

extern "C" void kernel_launch(void* const* d_in, const int* in_sizes, int n_in,
                              void* d_out, int out_size)
{
    const float* x_post = (const float*)d_in[0];
    const float* x_user = (const float*)d_in[1];
    const float* x_ent  = (const float*)d_in[2];
    const float* post_w = (const float*)d_in[15];
    const float* post_b = (const float*)d_in[16];
    const float* user_w = (const float*)d_in[17];
    const float* user_b = (const float*)d_in[18];
    const float* ent_w  = (const float*)d_in[19];
    const float* ent_b  = (const float*)d_in[20];
    const float* W_src  = (const float*)d_in[21];
    const float* W_dstP = (const float*)d_in[22];
    const float* a_srcP = (const float*)d_in[23];
    const float* a_dstP = (const float*)d_in[24];
    const float* gat_b  = (const float*)d_in[25];
    const float* cls_w1 = (const float*)d_in[26];
    const float* cls_b1 = (const float*)d_in[27];
    const float* cls_w2 = (const float*)d_in[28];
    const float* cls_b2 = (const float*)d_in[29];

    float *f0p,*f0u,*f0e,*f1p,*f1u,*f1e,*als,*ald,*sb,*ebuf,*ub;
    __nv_bfloat16 *xh, *xl;
    __half* hsb;
    cudaGetSymbolAddress((void**)&f0p, g_f0_post);
    cudaGetSymbolAddress((void**)&f0u, g_f0_user);
    cudaGetSymbolAddress((void**)&f0e, g_f0_ent);
    cudaGetSymbolAddress((void**)&f1p, g_f1_post);
    cudaGetSymbolAddress((void**)&f1u, g_f1_user);
    cudaGetSymbolAddress((void**)&f1e, g_f1_ent);
    cudaGetSymbolAddress((void**)&xh,  g_xh);
    cudaGetSymbolAddress((void**)&xl,  g_xl);
    cudaGetSymbolAddress((void**)&hsb, g_hs);
    cudaGetSymbolAddress((void**)&als, g_als);
    cudaGetSymbolAddress((void**)&ald, g_ald);
    cudaGetSymbolAddress((void**)&sb,  g_s);
    cudaGetSymbolAddress((void**)&ebuf,g_e);
    cudaGetSymbolAddress((void**)&ub,  g_u);

    const int ncnt[3] = { NUSER, NPOST, NENT };
    const int toff[3] = { 0, NUSER, NUSER + NPOST };

    int E[6], soff[6], doff[6], eoff[6];
    int sacc = 0, dacc = 0, eacc = 0;
    for (int r = 0; r < 6; r++) {
        E[r] = in_sizes[g_rels[r].sidx];
        soff[r] = sacc; sacc += ncnt[g_rels[r].stype];
        doff[r] = dacc; dacc += ncnt[g_rels[r].dtype];
        eoff[r] = eacc; eacc += E[r];
    }

    // fold attention vectors
    k_prep_u_all<<<12, 128>>>(a_srcP, a_dstP, W_src, W_dstP, ub);

    // input projections
    {
        GemmBatch pb;
        pb.J = 64; pb.nseg = 3;
        pb.seg[0] = { x_post, nullptr, nullptr, post_w, post_b, f0p, nullptr, NPOST, 768, 0 };
        pb.seg[1] = { x_user, nullptr, nullptr, user_w, user_b, f0u, nullptr, NUSER, 32, 0 };
        pb.seg[2] = { x_ent,  nullptr, nullptr, ent_w,  ent_b,  f0e, nullptr, NENT,  64, 0 };
        pb.off[0] = 0;
        pb.off[1] = pb.off[0] + cdiv(NPOST, 128);
        pb.off[2] = pb.off[1] + cdiv(NUSER, 128);
        pb.off[3] = pb.off[2] + cdiv(NENT, 128);
        k_gemm_t<0><<<dim3(pb.off[3], 1), 256>>>(pb);
    }

    float* cur[3] = { f0u, f0p, f0e };
    float* nxt[3] = { f1u, f1p, f1e };

    for (int l = 0; l < 2; l++) {
        int relu = (l == 1);

        // cvt + al + fused init
        {
            AlBatch ab;
            ab.seg[0].x = cur[0]; ab.seg[0].xh = xh + (size_t)toff[0]*64;
            ab.seg[0].xl = xl + (size_t)toff[0]*64;
            ab.seg[0].N = NUSER; ab.seg[0].relu = relu; ab.seg[0].njobs = 6;
            ab.seg[0].job[0] = { ub + (l*6+0)*256,       als + soff[0]*2 };
            ab.seg[0].job[1] = { ub + (l*6+1)*256,       als + soff[1]*2 };
            ab.seg[0].job[2] = { ub + (l*6+3)*256,       als + soff[3]*2 };
            ab.seg[0].job[3] = { ub + (l*6+3)*256 + 128, ald + doff[3]*2 };
            ab.seg[0].job[4] = { ub + (l*6+4)*256,       als + soff[4]*2 };
            ab.seg[0].job[5] = { ub + (l*6+4)*256 + 128, ald + doff[4]*2 };
            ab.seg[1].x = cur[1]; ab.seg[1].xh = xh + (size_t)toff[1]*64;
            ab.seg[1].xl = xl + (size_t)toff[1]*64;
            ab.seg[1].N = NPOST; ab.seg[1].relu = relu; ab.seg[1].njobs = 5;
            ab.seg[1].job[0] = { ub + (l*6+0)*256 + 128, ald + doff[0]*2 };
            ab.seg[1].job[1] = { ub + (l*6+1)*256 + 128, ald + doff[1]*2 };
            ab.seg[1].job[2] = { ub + (l*6+2)*256,       als + soff[2]*2 };
            ab.seg[1].job[3] = { ub + (l*6+5)*256,       als + soff[5]*2 };
            ab.seg[1].job[4] = { ub + (l*6+5)*256 + 128, ald + doff[5]*2 };
            ab.seg[1].job[5] = { nullptr, nullptr };
            ab.seg[2].x = cur[2]; ab.seg[2].xh = xh + (size_t)toff[2]*64;
            ab.seg[2].xl = xl + (size_t)toff[2]*64;
            ab.seg[2].N = NENT; ab.seg[2].relu = relu; ab.seg[2].njobs = 1;
            ab.seg[2].job[0] = { ub + (l*6+2)*256 + 128, ald + doff[2]*2 };
            for (int j = 1; j < 6; j++) ab.seg[2].job[j] = { nullptr, nullptr };
            ab.off[0] = 0;
            ab.off[1] = ab.off[0] + cdiv(NUSER, 128);
            ab.off[2] = ab.off[1] + cdiv(NPOST, 128);
            ab.off[3] = ab.off[2] + cdiv(NENT, 128);
            ab.nbP = nxt[1]; ab.nbU = nxt[0]; ab.nbE = nxt[2]; ab.s = sb;
            ab.bP0 = gat_b + (l*6+0)*64; ab.bP1 = gat_b + (l*6+1)*64;
            ab.bP2 = gat_b + (l*6+5)*64;
            ab.bU0 = gat_b + (l*6+3)*64; ab.bU1 = gat_b + (l*6+4)*64;
            ab.bE0 = gat_b + (l*6+2)*64;
            ab.iU  = (NPOST * 64) / 256;
            ab.iE  = ab.iU + (NUSER * 64) / 256;
            ab.iMS = ab.iE + (NENT * 64) / 256;
            int iEnd = ab.iMS + cdiv(DROWS * 2, 256);
            k_cvt_al_b<<<ab.off[3] + iEnd, 256>>>(ab);
        }

        // hs GEMMs
        {
            GemmBatch hb;
            hb.J = 128; hb.nseg = 6;
            int acc = 0;
            for (int r = 0; r < 6; r++) {
                int st = g_rels[r].stype;
                int Ns = ncnt[st];
                hb.seg[r] = { nullptr, xh + (size_t)toff[st]*64, xl + (size_t)toff[st]*64,
                              W_src + (size_t)(l*6+r)*128*64, nullptr, nullptr,
                              hsb + (size_t)soff[r]*128, Ns, 64, 0 };
                hb.off[r] = acc; acc += cdiv(Ns, 128);
            }
            hb.off[6] = acc;
            k_gemm_t<1><<<dim3(acc, 2), 256>>>(hb);
        }

        // edge passes
        {
            EdgeBatch eb2;
            int accA = 0, accC = 0;
            for (int r = 0; r < 6; r++) {
                eb2.seg[r].src = (const int*)d_in[g_rels[r].sidx];
                eb2.seg[r].dst = (const int*)d_in[g_rels[r].didx];
                eb2.seg[r].e   = ebuf + (size_t)eoff[r]*2;
                eb2.seg[r].als = als + soff[r]*2;
                eb2.seg[r].ald = ald + doff[r]*2;
                eb2.seg[r].s   = sb + doff[r]*2;
                eb2.seg[r].hs  = hsb + (size_t)soff[r]*128;
                eb2.seg[r].nb  = nxt[g_rels[r].dtype];
                eb2.seg[r].E   = E[r];
                eb2.offA[r] = accA; accA += cdiv(E[r], 256);
                eb2.offC[r] = accC; accC += cdiv(E[r] * 8, 256);
            }
            eb2.offA[6] = accA; eb2.offC[6] = accC;
            k_edge_ps<<<accA, 256>>>(eb2);
            k_edge_c_b<<<accC, 256>>>(eb2);
        }

        float* t;
        t = cur[0]; cur[0] = nxt[0]; nxt[0] = t;
        t = cur[1]; cur[1] = nxt[1]; nxt[1] = t;
        t = cur[2]; cur[2] = nxt[2]; nxt[2] = t;
    }

    k_cls<<<cdiv(NPOST, 256), 256>>>(cur[1], cls_w1, cls_b1, cls_w2, cls_b2,
                                     (float*)d_out, NPOST);
}